// round 1
// baseline (speedup 1.0000x reference)
#include <cuda_runtime.h>
#include <cstdint>

// out[t, h] = W[h, seq[t]] + b[h]
// seq: int32 [n_tok], W: fp32 [H, V] row-major, b: fp32 [H], out: fp32 [n_tok, H]

#define H_DIM 1024
#define TOK_PER_BLK 16
#define THREADS 256

__global__ __launch_bounds__(THREADS)
void onehot_gather_kernel(const int* __restrict__ seq,
                          const float* __restrict__ W,
                          const float* __restrict__ bias,
                          float* __restrict__ out,
                          int n_tok, int V) {
    __shared__ int s_tok[TOK_PER_BLK];

    const int base = blockIdx.x * TOK_PER_BLK;
    if (threadIdx.x < TOK_PER_BLK) {
        int t = base + threadIdx.x;
        s_tok[threadIdx.x] = (t < n_tok) ? seq[t] : 0;
    }

    // Each thread owns 4 consecutive hidden dims -> one float4 store per token.
    const int h0 = threadIdx.x * 4;                // 256 threads * 4 = 1024 = H_DIM
    const float4 b4 = *reinterpret_cast<const float4*>(bias + h0);

    __syncthreads();

    const float* __restrict__ Wr = W + (size_t)h0 * (size_t)V;
    const size_t Vs = (size_t)V;

    #pragma unroll
    for (int j = 0; j < TOK_PER_BLK; j++) {
        int t = base + j;
        if (t >= n_tok) break;
        const int v = s_tok[j];

        float4 r;
        r.x = __ldg(Wr + v)          + b4.x;
        r.y = __ldg(Wr + Vs + v)     + b4.y;
        r.z = __ldg(Wr + 2 * Vs + v) + b4.z;
        r.w = __ldg(Wr + 3 * Vs + v) + b4.w;

        // Streaming store: output is write-once, keep W resident in L2.
        float4* dst = reinterpret_cast<float4*>(out + (size_t)t * H_DIM + h0);
        __stcs(dst, r);
    }
}

extern "C" void kernel_launch(void* const* d_in, const int* in_sizes, int n_in,
                              void* d_out, int out_size) {
    const int*   seq  = (const int*)d_in[0];
    const float* W    = (const float*)d_in[1];
    const float* bias = (const float*)d_in[2];
    float*       out  = (float*)d_out;

    const int n_tok = in_sizes[0];              // 8 * 4096 = 32768
    const int H     = in_sizes[2];              // 1024
    const int V     = in_sizes[1] / H;          // 50257
    (void)H; (void)out_size; (void)n_in;

    const int blocks = (n_tok + TOK_PER_BLK - 1) / TOK_PER_BLK;
    onehot_gather_kernel<<<blocks, THREADS>>>(seq, W, bias, out, n_tok, V);
}

// round 2
// speedup vs baseline: 1.9642x; 1.9642x over previous
#include <cuda_runtime.h>
#include <cstdint>

// out[t, h] = W[h, seq[t]] + b[h]
// seq: int32 [n_tok], W: fp32 [H, V] row-major, b: fp32 [H], out: fp32 [n_tok, H]
//
// Strategy: counting-sort tokens by value bucket (v>>3 == one 32B sector),
// then gather W in near-sequential v order so each W sector is pulled from
// HBM exactly once (201MB instead of ~2.5GB measured for random order).

#define H_DIM 1024
#define TOK_PER_BLK 32
#define THREADS 256

#define MAX_N 65536
#define MAX_BUCKETS 8192
#define SCAN_THREADS 1024
#define SCAN_PER 8            // 1024*8 = 8192 >= MAX_BUCKETS

__device__ int g_hist[MAX_BUCKETS];
__device__ int g_off[MAX_BUCKETS];
__device__ int g_sorted_v[MAX_N];
__device__ int g_sorted_t[MAX_N];

// ---------------- sort pipeline ----------------

__global__ void zero_hist_kernel(int nbuckets) {
    int i = blockIdx.x * blockDim.x + threadIdx.x;
    if (i < nbuckets) g_hist[i] = 0;
}

__global__ void hist_kernel(const int* __restrict__ seq, int n) {
    int i = blockIdx.x * blockDim.x + threadIdx.x;
    if (i < n) {
        int v = seq[i];
        atomicAdd(&g_hist[v >> 3], 1);
    }
}

__global__ __launch_bounds__(SCAN_THREADS)
void scan_kernel(int nbuckets) {
    __shared__ int warp_sums[32];
    const int tid  = threadIdx.x;
    const int lane = tid & 31;
    const int w    = tid >> 5;

    int vals[SCAN_PER];
    int local = 0;
    #pragma unroll
    for (int i = 0; i < SCAN_PER; i++) {
        int idx = tid * SCAN_PER + i;
        vals[i] = (idx < nbuckets) ? g_hist[idx] : 0;
        local += vals[i];
    }

    // warp inclusive scan of per-thread sums
    int x = local;
    #pragma unroll
    for (int d = 1; d < 32; d <<= 1) {
        int y = __shfl_up_sync(0xFFFFFFFFu, x, d);
        if (lane >= d) x += y;
    }
    if (lane == 31) warp_sums[w] = x;
    __syncthreads();

    if (w == 0) {
        int s = warp_sums[lane];
        #pragma unroll
        for (int d = 1; d < 32; d <<= 1) {
            int y = __shfl_up_sync(0xFFFFFFFFu, s, d);
            if (lane >= d) s += y;
        }
        warp_sums[lane] = s;  // inclusive scan of warp sums
    }
    __syncthreads();

    int thread_excl = (w > 0 ? warp_sums[w - 1] : 0) + (x - local);

    int run = thread_excl;
    #pragma unroll
    for (int i = 0; i < SCAN_PER; i++) {
        int idx = tid * SCAN_PER + i;
        if (idx < nbuckets) g_off[idx] = run;
        run += vals[i];
    }
}

__global__ void scatter_kernel(const int* __restrict__ seq, int n) {
    int t = blockIdx.x * blockDim.x + threadIdx.x;
    if (t < n) {
        int v = seq[t];
        int pos = atomicAdd(&g_off[v >> 3], 1);
        g_sorted_v[pos] = v;
        g_sorted_t[pos] = t;
    }
}

// ---------------- main gather ----------------

__global__ __launch_bounds__(THREADS)
void onehot_gather_sorted_kernel(const float* __restrict__ W,
                                 const float* __restrict__ bias,
                                 float* __restrict__ out,
                                 int n_tok, int V) {
    __shared__ int s_v[TOK_PER_BLK];
    __shared__ int s_t[TOK_PER_BLK];

    const int base = blockIdx.x * TOK_PER_BLK;
    if (threadIdx.x < TOK_PER_BLK) {
        int j = base + threadIdx.x;
        s_v[threadIdx.x] = (j < n_tok) ? g_sorted_v[j] : -1;
        s_t[threadIdx.x] = (j < n_tok) ? g_sorted_t[j] : 0;
    }

    // Each thread owns 4 consecutive hidden dims -> one float4 store per token.
    const int h0 = threadIdx.x * 4;  // 256 threads * 4 = 1024 = H_DIM
    const float4 b4 = *reinterpret_cast<const float4*>(bias + h0);

    __syncthreads();

    const float* __restrict__ Wr = W + (size_t)h0 * (size_t)V;
    const size_t Vs = (size_t)V;

    int prev_v = -1;
    float4 r = b4;

    #pragma unroll 4
    for (int j = 0; j < TOK_PER_BLK; j++) {
        if (base + j >= n_tok) break;
        const int v = s_v[j];
        const int t = s_t[j];

        if (v != prev_v) {
            r.x = __ldg(Wr + v)          + b4.x;
            r.y = __ldg(Wr + Vs + v)     + b4.y;
            r.z = __ldg(Wr + 2 * Vs + v) + b4.z;
            r.w = __ldg(Wr + 3 * Vs + v) + b4.w;
            prev_v = v;
        }

        float4* dst = reinterpret_cast<float4*>(out + (size_t)t * H_DIM + h0);
        __stcs(dst, r);
    }
}

// ---------------- launch ----------------

extern "C" void kernel_launch(void* const* d_in, const int* in_sizes, int n_in,
                              void* d_out, int out_size) {
    const int*   seq  = (const int*)d_in[0];
    const float* W    = (const float*)d_in[1];
    const float* bias = (const float*)d_in[2];
    float*       out  = (float*)d_out;

    const int n_tok = in_sizes[0];            // 32768
    const int H     = in_sizes[2];            // 1024
    const int V     = in_sizes[1] / H;        // 50257
    const int nbuckets = (V + 7) >> 3;        // 6283
    (void)out_size; (void)n_in;

    zero_hist_kernel<<<(nbuckets + 1023) / 1024, 1024>>>(nbuckets);
    hist_kernel<<<(n_tok + 255) / 256, 256>>>(seq, n_tok);
    scan_kernel<<<1, SCAN_THREADS>>>(nbuckets);
    scatter_kernel<<<(n_tok + 255) / 256, 256>>>(seq, n_tok);

    const int blocks = (n_tok + TOK_PER_BLK - 1) / TOK_PER_BLK;
    onehot_gather_sorted_kernel<<<blocks, THREADS>>>(W, bias, out, n_tok, V);
}

// round 3
// speedup vs baseline: 6.0346x; 3.0723x over previous
#include <cuda_runtime.h>
#include <cstdint>

// out[t, h] = W[h, seq[t]] + b[h]
// seq: int32 [n_tok], W: fp32 [H, V] row-major, b: fp32 [H], out: fp32 [n_tok, H]
//
// Pipeline:
//  1-4) counting-sort tokens by sector bucket (v>>3) so token values are
//       nearly sorted -> W is swept almost sequentially.
//  5)   gather kernel: load phase puts warp lanes ALONG sorted values
//       (divergent LDG collapses to ~6 sectors/warp instead of 32),
//       transposes through padded SMEM, store phase writes fully
//       coalesced 128B rows per warp.

#define H_DIM 1024
#define TOK_PER_BLK 32
#define THREADS 256
#define HCHUNK 128
#define NCHUNK (H_DIM / HCHUNK)   // 8

#define MAX_N 65536
#define MAX_BUCKETS 8192
#define SCAN_THREADS 1024
#define SCAN_PER 8                 // 1024*8 = 8192 >= MAX_BUCKETS

__device__ int g_hist[MAX_BUCKETS];
__device__ int g_off[MAX_BUCKETS];
__device__ int g_sorted_v[MAX_N];
__device__ int g_sorted_t[MAX_N];

// ---------------- sort pipeline ----------------

__global__ void zero_hist_kernel(int nbuckets) {
    int i = blockIdx.x * blockDim.x + threadIdx.x;
    if (i < nbuckets) g_hist[i] = 0;
}

__global__ void hist_kernel(const int* __restrict__ seq, int n) {
    int i = blockIdx.x * blockDim.x + threadIdx.x;
    if (i < n) {
        int v = seq[i];
        atomicAdd(&g_hist[v >> 3], 1);
    }
}

__global__ __launch_bounds__(SCAN_THREADS)
void scan_kernel(int nbuckets) {
    __shared__ int warp_sums[32];
    const int tid  = threadIdx.x;
    const int lane = tid & 31;
    const int w    = tid >> 5;

    int vals[SCAN_PER];
    int local = 0;
    #pragma unroll
    for (int i = 0; i < SCAN_PER; i++) {
        int idx = tid * SCAN_PER + i;
        vals[i] = (idx < nbuckets) ? g_hist[idx] : 0;
        local += vals[i];
    }

    int x = local;
    #pragma unroll
    for (int d = 1; d < 32; d <<= 1) {
        int y = __shfl_up_sync(0xFFFFFFFFu, x, d);
        if (lane >= d) x += y;
    }
    if (lane == 31) warp_sums[w] = x;
    __syncthreads();

    if (w == 0) {
        int s = warp_sums[lane];
        #pragma unroll
        for (int d = 1; d < 32; d <<= 1) {
            int y = __shfl_up_sync(0xFFFFFFFFu, s, d);
            if (lane >= d) s += y;
        }
        warp_sums[lane] = s;
    }
    __syncthreads();

    int thread_excl = (w > 0 ? warp_sums[w - 1] : 0) + (x - local);

    int run = thread_excl;
    #pragma unroll
    for (int i = 0; i < SCAN_PER; i++) {
        int idx = tid * SCAN_PER + i;
        if (idx < nbuckets) g_off[idx] = run;
        run += vals[i];
    }
}

__global__ void scatter_kernel(const int* __restrict__ seq, int n) {
    int t = blockIdx.x * blockDim.x + threadIdx.x;
    if (t < n) {
        int v = seq[t];
        int pos = atomicAdd(&g_off[v >> 3], 1);
        g_sorted_v[pos] = v;
        g_sorted_t[pos] = t;
    }
}

// ---------------- main gather ----------------

__global__ __launch_bounds__(THREADS)
void onehot_gather_xpose_kernel(const float* __restrict__ W,
                                const float* __restrict__ bias,
                                float* __restrict__ out,
                                int n_tok, int V) {
    __shared__ float s_w[HCHUNK][TOK_PER_BLK + 1];  // pad -> conflict-free both phases
    __shared__ int s_t[TOK_PER_BLK];
    __shared__ int s_v[TOK_PER_BLK];

    const int tid  = threadIdx.x;
    const int lane = tid & 31;
    const int w    = tid >> 5;
    const int base = blockIdx.x * TOK_PER_BLK;

    if (tid < TOK_PER_BLK) {
        int j = base + tid;
        s_v[tid] = (j < n_tok) ? g_sorted_v[j] : 0;   // clamp: valid addr
        s_t[tid] = (j < n_tok) ? g_sorted_t[j] : -1;  // -1 -> skip store
    }
    __syncthreads();

    // Load phase lane owns token 'lane' of this block (values sorted ->
    // lanes hit few sectors; duplicates merge inside the LDG).
    const int my_v = s_v[lane];

    // Store phase: warp w owns tokens 4w..4w+3.
    int st_t[4];
    #pragma unroll
    for (int q = 0; q < 4; q++) st_t[q] = s_t[(w << 2) + q];

    for (int c = 0; c < NCHUNK; c++) {
        const int h_base = c * HCHUNK;

        // ---- load phase: 16 independent gathers per thread ----
        #pragma unroll
        for (int i = 0; i < 16; i++) {
            int h_local = (i << 3) + w;  // warp w covers h_local = w, w+8, ...
            float val = __ldg(W + (size_t)(h_base + h_local) * (size_t)V + my_v);
            s_w[h_local][lane] = val;    // stride-1 across lanes: conflict-free
        }

        // bias for this lane's 4 h positions in the chunk
        float bl[4];
        #pragma unroll
        for (int hs = 0; hs < 4; hs++)
            bl[hs] = __ldg(bias + h_base + (hs << 5) + lane);

        __syncthreads();

        // ---- store phase: coalesced 128B rows ----
        #pragma unroll
        for (int q = 0; q < 4; q++) {
            const int j = (w << 2) + q;
            const int t = st_t[q];
            if (t < 0) continue;
            float* dst = out + (size_t)t * H_DIM + h_base;
            #pragma unroll
            for (int hs = 0; hs < 4; hs++) {
                int h_local = (hs << 5) + lane;
                float r = s_w[h_local][j] + bl[hs];  // stride-33: conflict-free
                __stcs(dst + h_local, r);
            }
        }
        __syncthreads();
    }
}

// ---------------- launch ----------------

extern "C" void kernel_launch(void* const* d_in, const int* in_sizes, int n_in,
                              void* d_out, int out_size) {
    const int*   seq  = (const int*)d_in[0];
    const float* W    = (const float*)d_in[1];
    const float* bias = (const float*)d_in[2];
    float*       out  = (float*)d_out;

    const int n_tok = in_sizes[0];            // 32768
    const int H     = in_sizes[2];            // 1024
    const int V     = in_sizes[1] / H;        // 50257
    const int nbuckets = (V + 7) >> 3;        // 6283
    (void)out_size; (void)n_in;

    zero_hist_kernel<<<(nbuckets + 1023) / 1024, 1024>>>(nbuckets);
    hist_kernel<<<(n_tok + 255) / 256, 256>>>(seq, n_tok);
    scan_kernel<<<1, SCAN_THREADS>>>(nbuckets);
    scatter_kernel<<<(n_tok + 255) / 256, 256>>>(seq, n_tok);

    const int blocks = (n_tok + TOK_PER_BLK - 1) / TOK_PER_BLK;
    onehot_gather_xpose_kernel<<<blocks, THREADS>>>(W, bias, out, n_tok, V);
}